// round 3
// baseline (speedup 1.0000x reference)
#include <cuda_runtime.h>
#include <cuda_fp16.h>
#include <cstdint>

#define MDIM 4096
#define KDIM 4096
#define NDIM 11008
#define BM 128
#define BN 128
#define BK 64
#define NKC (KDIM / BK)      // 64
#define NT 256

#define SA_BYTES (BM * BK * 2)          // 16384
#define SB_BYTES (BN * BK * 2)          // 16384
#define STAGE_BYTES (SA_BYTES + SB_BYTES)   // 32768
#define SMEM_BYTES (2 * STAGE_BYTES)        // 65536

__device__ __forceinline__ uint32_t smem_u32(const void* p) {
    uint32_t a;
    asm("{ .reg .u64 t; cvta.to.shared.u64 t, %1; cvt.u32.u64 %0, t; }" : "=r"(a) : "l"(p));
    return a;
}

__device__ __forceinline__ void ldsm4(uint32_t& r0, uint32_t& r1, uint32_t& r2, uint32_t& r3,
                                      uint32_t addr) {
    asm volatile("ldmatrix.sync.aligned.m8n8.x4.shared.b16 {%0,%1,%2,%3}, [%4];"
                 : "=r"(r0), "=r"(r1), "=r"(r2), "=r"(r3) : "r"(addr));
}

__device__ __forceinline__ void mma16816(float* c, const uint32_t* a, const uint32_t* b) {
    asm volatile(
        "mma.sync.aligned.m16n8k16.row.col.f32.f16.f16.f32 "
        "{%0,%1,%2,%3}, {%4,%5,%6,%7}, {%8,%9}, {%0,%1,%2,%3};"
        : "+f"(c[0]), "+f"(c[1]), "+f"(c[2]), "+f"(c[3])
        : "r"(a[0]), "r"(a[1]), "r"(a[2]), "r"(a[3]), "r"(b[0]), "r"(b[1]));
}

__global__ __launch_bounds__(NT, 1)
void aql_gemm(const float* __restrict__ x, const int* __restrict__ wp,
              const float* __restrict__ scale, const float* __restrict__ zero,
              float* __restrict__ out)
{
    extern __shared__ char smem[];
    const uint32_t sb = smem_u32(smem);
    const int t = threadIdx.x;

    // ---- grouped tile rasterization: GROUP_M=8 m-tiles per n sweep ----
    const int NPID_N = NDIM / BN;   // 86
    const int GROUP = 8;            // 32 m-tiles divisible by 8
    int pid = blockIdx.x;
    int gsz = GROUP * NPID_N;       // 688
    int g = pid / gsz;
    int rem = pid - g * gsz;
    int m_tile = g * GROUP + (rem % GROUP);
    int n_tile = rem / GROUP;
    const int m0 = m_tile * BM;
    const int n0 = n_tile * BN;

    // ---- per-thread load-geometry constants ----
    // A: chunk-id c: idx = t + c*256; m = idx>>3 (0..127), kc8 = idx&7 (16B chunk within row)
    // B: n = t&127 (fixed), kb = (t>>7) + c*2
    const int bn = t & 127;
    const float zr = zero[n0 + bn];
    const __half2 bias = __float2half2_rn(1024.0f + zr);   // exact (integer <= 1039)

    const float* aptr[4];
    uint32_t sA_sts[4];
    #pragma unroll
    for (int c = 0; c < 4; c++) {
        int idx = t + c * NT;
        int m = idx >> 3, kc8 = idx & 7;
        aptr[c] = x + (size_t)(m0 + m) * KDIM + kc8 * 8;
        sA_sts[c] = sb + m * 128 + ((kc8 ^ (m & 7)) << 4);
    }
    const int* bptr[4];
    uint32_t sB_sts[4];
    #pragma unroll
    for (int c = 0; c < 4; c++) {
        int kb = (t >> 7) + c * 2;
        bptr[c] = wp + (size_t)(kb * 4) * NDIM + n0 + bn;
        sB_sts[c] = sb + SA_BYTES + bn * 128 + ((kb ^ (bn & 7)) << 4);
    }

    // ---- ldmatrix lane base addresses ----
    const int wid = t >> 5, lane = t & 31;
    const int wm = (wid >> 2) * 64;     // warp m offset (2 rows of warps)
    const int wn = (wid & 3) * 32;      // warp n offset (4 cols of warps)
    const int lg = lane >> 3, lr = lane & 7;
    const int kA = lg >> 1;             // A: kc8 = 2*ks + (lg>>1)
    const int kB = lg & 1;              // B: kc8 = 2*ks + (lg&1)

    uint32_t a_base[4], b_base[2];
    #pragma unroll
    for (int i = 0; i < 4; i++) {
        int m = wm + i * 16 + ((lg & 1) << 3) + lr;
        a_base[i] = sb + m * 128 + ((m & 7) << 4);
    }
    #pragma unroll
    for (int j = 0; j < 2; j++) {
        int n = wn + j * 16 + ((lg >> 1) << 3) + lr;
        b_base[j] = sb + SA_BYTES + n * 128 + ((n & 7) << 4);
    }

    // ---- staging registers ----
    float4 ra[4][2];
    int rb[4][4];

    auto ldg_chunk = [&](int kc) {
        #pragma unroll
        for (int c = 0; c < 4; c++) {
            const float4* p = reinterpret_cast<const float4*>(aptr[c] + kc * BK);
            ra[c][0] = p[0];
            ra[c][1] = p[1];
        }
        #pragma unroll
        for (int c = 0; c < 4; c++) {
            const int* p = bptr[c] + (size_t)kc * 32 * NDIM;
            #pragma unroll
            for (int j = 0; j < 4; j++) rb[c][j] = p[(size_t)j * NDIM];
        }
    };

    auto sts_chunk = [&](uint32_t buf) {
        #pragma unroll
        for (int c = 0; c < 4; c++) {
            uint32_t h[4];
            __half2 h0 = __floats2half2_rn(ra[c][0].x, ra[c][0].y);
            __half2 h1 = __floats2half2_rn(ra[c][0].z, ra[c][0].w);
            __half2 h2 = __floats2half2_rn(ra[c][1].x, ra[c][1].y);
            __half2 h3 = __floats2half2_rn(ra[c][1].z, ra[c][1].w);
            h[0] = *reinterpret_cast<uint32_t*>(&h0);
            h[1] = *reinterpret_cast<uint32_t*>(&h1);
            h[2] = *reinterpret_cast<uint32_t*>(&h2);
            h[3] = *reinterpret_cast<uint32_t*>(&h3);
            asm volatile("st.shared.v4.b32 [%0], {%1,%2,%3,%4};"
                         :: "r"(sA_sts[c] + buf), "r"(h[0]), "r"(h[1]), "r"(h[2]), "r"(h[3]));
        }
        #pragma unroll
        for (int c = 0; c < 4; c++) {
            uint32_t w[4];
            #pragma unroll
            for (int j = 0; j < 4; j++) {
                uint32_t v = (uint32_t)rb[c][j];
                uint32_t pk = 0x64006400u | (v & 0xFu) | ((v & 0xF0u) << 12);
                __half2 hv = __hsub2(*reinterpret_cast<__half2*>(&pk), bias);
                w[j] = *reinterpret_cast<uint32_t*>(&hv);
            }
            asm volatile("st.shared.v4.b32 [%0], {%1,%2,%3,%4};"
                         :: "r"(sB_sts[c] + buf), "r"(w[0]), "r"(w[1]), "r"(w[2]), "r"(w[3]));
        }
    };

    float acc[4][4][4];
    #pragma unroll
    for (int i = 0; i < 4; i++)
        #pragma unroll
        for (int j = 0; j < 4; j++)
            #pragma unroll
            for (int r = 0; r < 4; r++) acc[i][j][r] = 0.0f;

    // ---- prologue ----
    ldg_chunk(0);
    sts_chunk(0);
    ldg_chunk(1);
    __syncthreads();

    // ---- main loop ----
    for (int kc = 0; kc < NKC; kc++) {
        const uint32_t buf = (kc & 1) ? STAGE_BYTES : 0;
        #pragma unroll
        for (int ks = 0; ks < 4; ks++) {
            uint32_t a[4][4], b[4][2];
            #pragma unroll
            for (int i = 0; i < 4; i++)
                ldsm4(a[i][0], a[i][1], a[i][2], a[i][3],
                      (a_base[i] + buf) ^ (((ks << 1) + kA) << 4));
            #pragma unroll
            for (int j = 0; j < 2; j++) {
                uint32_t r0, r1, r2, r3;
                ldsm4(r0, r1, r2, r3, (b_base[j] + buf) ^ (((ks << 1) + kB) << 4));
                b[2 * j][0] = r0; b[2 * j][1] = r1;
                b[2 * j + 1][0] = r2; b[2 * j + 1][1] = r3;
            }
            #pragma unroll
            for (int i = 0; i < 4; i++)
                #pragma unroll
                for (int j = 0; j < 4; j++)
                    mma16816(acc[i][j], a[i], b[j]);
        }
        if (kc + 1 < NKC) {
            __syncthreads();
            sts_chunk((kc & 1) ? 0 : STAGE_BYTES);
            if (kc + 2 < NKC) ldg_chunk(kc + 2);
            __syncthreads();
        }
    }

    // ---- epilogue: scale columns, store fp32 ----
    const int qr = lane >> 2, qc = lane & 3;
    float s0[4], s1[4];
    #pragma unroll
    for (int j = 0; j < 4; j++) {
        int c = n0 + wn + j * 8 + qc * 2;
        s0[j] = __ldg(&scale[c]);
        s1[j] = __ldg(&scale[c + 1]);
    }
    #pragma unroll
    for (int i = 0; i < 4; i++) {
        int rlo = m0 + wm + i * 16 + qr;
        #pragma unroll
        for (int j = 0; j < 4; j++) {
            int c = n0 + wn + j * 8 + qc * 2;
            float2 v;
            v.x = acc[i][j][0] * s0[j];
            v.y = acc[i][j][1] * s1[j];
            *reinterpret_cast<float2*>(out + (size_t)rlo * NDIM + c) = v;
            v.x = acc[i][j][2] * s0[j];
            v.y = acc[i][j][3] * s1[j];
            *reinterpret_cast<float2*>(out + (size_t)(rlo + 8) * NDIM + c) = v;
        }
    }
}

extern "C" void kernel_launch(void* const* d_in, const int* in_sizes, int n_in,
                              void* d_out, int out_size)
{
    const float* x     = (const float*)d_in[0];
    const int*   wp    = (const int*)d_in[1];
    const float* scale = (const float*)d_in[2];
    const float* zero  = (const float*)d_in[3];
    float* out = (float*)d_out;

    cudaFuncSetAttribute(aql_gemm, cudaFuncAttributeMaxDynamicSharedMemorySize,
                         (int)SMEM_BYTES);
    int grid = (MDIM / BM) * (NDIM / BN);   // 2752
    aql_gemm<<<grid, NT, SMEM_BYTES>>>(x, wp, scale, zero, out);
}

// round 4
// speedup vs baseline: 1.1081x; 1.1081x over previous
#include <cuda_runtime.h>
#include <cuda_fp16.h>
#include <cstdint>

#define MDIM 4096
#define KDIM 4096
#define NDIM 11008
#define BM 128
#define BN 128
#define BK 64
#define NKC (KDIM / BK)          // 64
#define NT 256                   // 4 consumer warps + 4 producer warps
#define NSTAGE 4

#define SA_BYTES (BM * BK * 2)   // 16384
#define STAGE_BYTES (2 * SA_BYTES)          // 32768 (A + B)
#define OFF_TILES 1024u
#define SMEM_BYTES (OFF_TILES + NSTAGE * STAGE_BYTES)   // 132096

// mbarriers: full[s] at s*8, empty[s] at 64 + s*8
#define MB_FULL(s)  ((uint32_t)((s) * 8))
#define MB_EMPTY(s) ((uint32_t)(64 + (s) * 8))

__device__ __forceinline__ uint32_t smem_u32(const void* p) {
    uint32_t a;
    asm("{ .reg .u64 t; cvta.to.shared.u64 t, %1; cvt.u32.u64 %0, t; }" : "=r"(a) : "l"(p));
    return a;
}

__device__ __forceinline__ void mbar_init(uint32_t addr, uint32_t cnt) {
    asm volatile("mbarrier.init.shared.b64 [%0], %1;" :: "r"(addr), "r"(cnt) : "memory");
}

__device__ __forceinline__ void mbar_arrive(uint32_t addr) {
    asm volatile("mbarrier.arrive.shared.b64 _, [%0];" :: "r"(addr) : "memory");
}

__device__ __forceinline__ void mbar_wait(uint32_t addr, uint32_t parity) {
    uint32_t done;
    asm volatile(
        "{\n .reg .pred p;\n"
        " mbarrier.try_wait.parity.shared.b64 p, [%1], %2;\n"
        " selp.b32 %0, 1, 0, p;\n}"
        : "=r"(done) : "r"(addr), "r"(parity) : "memory");
    while (!done) {
        asm volatile(
            "{\n .reg .pred p;\n"
            " mbarrier.try_wait.parity.shared.b64 p, [%1], %2, 0x989680;\n"
            " selp.b32 %0, 1, 0, p;\n}"
            : "=r"(done) : "r"(addr), "r"(parity) : "memory");
    }
}

__device__ __forceinline__ void ldsm4(uint32_t& r0, uint32_t& r1, uint32_t& r2, uint32_t& r3,
                                      uint32_t addr) {
    asm volatile("ldmatrix.sync.aligned.m8n8.x4.shared.b16 {%0,%1,%2,%3}, [%4];"
                 : "=r"(r0), "=r"(r1), "=r"(r2), "=r"(r3) : "r"(addr));
}

__device__ __forceinline__ void mma16816(float* c, const uint32_t* a, const uint32_t* b) {
    asm volatile(
        "mma.sync.aligned.m16n8k16.row.col.f32.f16.f16.f32 "
        "{%0,%1,%2,%3}, {%4,%5,%6,%7}, {%8,%9}, {%0,%1,%2,%3};"
        : "+f"(c[0]), "+f"(c[1]), "+f"(c[2]), "+f"(c[3])
        : "r"(a[0]), "r"(a[1]), "r"(a[2]), "r"(a[3]), "r"(b[0]), "r"(b[1]));
}

__global__ __launch_bounds__(NT, 1)
void aql_gemm(const float* __restrict__ x, const int* __restrict__ wp,
              const float* __restrict__ scale, const float* __restrict__ zero,
              float* __restrict__ out)
{
    extern __shared__ char smem[];
    const uint32_t sb = smem_u32(smem);
    const int t = threadIdx.x;

    // grouped rasterization (keep L2 reuse: DRAM was 4.7%)
    const int NPID_N = NDIM / BN;    // 86
    const int GROUP = 8;
    int pid = blockIdx.x;
    int gsz = GROUP * NPID_N;
    int g = pid / gsz;
    int rem = pid - g * gsz;
    const int m0 = (g * GROUP + (rem % GROUP)) * BM;
    const int n0 = (rem / GROUP) * BN;

    if (t == 0) {
        #pragma unroll
        for (int s = 0; s < NSTAGE; s++) {
            mbar_init(sb + MB_FULL(s), 128);   // 128 producer threads
            mbar_init(sb + MB_EMPTY(s), 128);  // 128 consumer threads
        }
    }
    __syncthreads();

    if (t >= 128) {
        // ================= PRODUCER (warps 4-7) =================
        const int ptid = t - 128;                 // 0..127
        // A geometry: q8 = 16B chunk in row (fixed), rows r = (ptid>>3) + c*16
        const int q8 = ptid & 7;
        const int r0r = ptid >> 3;                // 0..15
        const float* agp = x + (size_t)(m0 + r0r) * KDIM + q8 * 8;
        // B geometry: one column per thread
        const int bn = ptid;
        const int* bgp = wp + n0 + bn;
        const float zr = zero[n0 + bn];
        const __half2 bias = __float2half2_rn(1024.0f + zr);   // exact integer <= 1039

        uint32_t sA_sts[8];
        #pragma unroll
        for (int c = 0; c < 8; c++) {
            int r = r0r + c * 16;
            sA_sts[c] = sb + OFF_TILES + r * 128 + ((q8 ^ (r & 7)) << 4);
        }
        uint32_t sB_sts[8];
        #pragma unroll
        for (int gg = 0; gg < 8; gg++) {
            sB_sts[gg] = sb + OFF_TILES + SA_BYTES + bn * 128 + ((gg ^ (bn & 7)) << 4);
        }

        float4 ra[8][2];
        int rb[32];

        auto ldg_chunk = [&](int kc) {
            const float* ap = agp + kc * BK;
            #pragma unroll
            for (int c = 0; c < 8; c++) {
                const float4* p = reinterpret_cast<const float4*>(ap + (size_t)c * 16 * KDIM);
                ra[c][0] = p[0];
                ra[c][1] = p[1];
            }
            const int* bp = bgp + (size_t)(kc * 32) * NDIM;
            #pragma unroll
            for (int p = 0; p < 32; p++) rb[p] = bp[(size_t)p * NDIM];
        };

        ldg_chunk(0);
        uint32_t phase = 1;                       // first empty-wait passes immediately
        for (int kc = 0; kc < NKC; kc++) {
            const int s = kc & (NSTAGE - 1);
            const uint32_t so = (uint32_t)s * STAGE_BYTES;
            mbar_wait(sb + MB_EMPTY(s), phase);
            // A convert + STS
            #pragma unroll
            for (int c = 0; c < 8; c++) {
                __half2 h0 = __floats2half2_rn(ra[c][0].x, ra[c][0].y);
                __half2 h1 = __floats2half2_rn(ra[c][0].z, ra[c][0].w);
                __half2 h2 = __floats2half2_rn(ra[c][1].x, ra[c][1].y);
                __half2 h3 = __floats2half2_rn(ra[c][1].z, ra[c][1].w);
                asm volatile("st.shared.v4.b32 [%0], {%1,%2,%3,%4};"
                             :: "r"(sA_sts[c] + so),
                                "r"(*reinterpret_cast<uint32_t*>(&h0)),
                                "r"(*reinterpret_cast<uint32_t*>(&h1)),
                                "r"(*reinterpret_cast<uint32_t*>(&h2)),
                                "r"(*reinterpret_cast<uint32_t*>(&h3)));
            }
            // B dequant + STS (4 packed rows -> one 16B store of 8 halves)
            #pragma unroll
            for (int gg = 0; gg < 8; gg++) {
                uint32_t w[4];
                #pragma unroll
                for (int j = 0; j < 4; j++) {
                    uint32_t v = (uint32_t)rb[gg * 4 + j];
                    uint32_t pk = 0x64006400u | (v & 0xFu) | ((v & 0xF0u) << 12);
                    __half2 hv = __hsub2(*reinterpret_cast<__half2*>(&pk), bias);
                    w[j] = *reinterpret_cast<uint32_t*>(&hv);
                }
                asm volatile("st.shared.v4.b32 [%0], {%1,%2,%3,%4};"
                             :: "r"(sB_sts[gg] + so), "r"(w[0]), "r"(w[1]), "r"(w[2]), "r"(w[3]));
            }
            mbar_arrive(sb + MB_FULL(s));
            if (kc + 1 < NKC) ldg_chunk(kc + 1);
            if (s == NSTAGE - 1) phase ^= 1;
        }
        return;
    }

    // ================= CONSUMER (warps 0-3) =================
    const int wid = t >> 5, lane = t & 31;
    const int wm = (wid >> 1) * 64;
    const int wn = (wid & 1) * 64;
    const int lg = lane >> 3, lr = lane & 7;
    const int kA = lg >> 1;
    const int kB = lg & 1;

    uint32_t a_base[4], b_base[4];
    #pragma unroll
    for (int i = 0; i < 4; i++) {
        int m = wm + i * 16 + ((lg & 1) << 3) + lr;
        a_base[i] = sb + OFF_TILES + m * 128 + ((m & 7) << 4);
    }
    #pragma unroll
    for (int j = 0; j < 4; j++) {
        int n = wn + j * 16 + ((lg >> 1) << 3) + lr;
        b_base[j] = sb + OFF_TILES + SA_BYTES + n * 128 + ((n & 7) << 4);
    }

    float acc[4][8][4];
    #pragma unroll
    for (int i = 0; i < 4; i++)
        #pragma unroll
        for (int j = 0; j < 8; j++)
            #pragma unroll
            for (int r = 0; r < 4; r++) acc[i][j][r] = 0.0f;

    uint32_t phase = 0;
    for (int kc = 0; kc < NKC; kc++) {
        const int s = kc & (NSTAGE - 1);
        const uint32_t so = (uint32_t)s * STAGE_BYTES;
        mbar_wait(sb + MB_FULL(s), phase);
        #pragma unroll
        for (int ks = 0; ks < 4; ks++) {
            uint32_t a[4][4], b[8][2];
            #pragma unroll
            for (int i = 0; i < 4; i++)
                ldsm4(a[i][0], a[i][1], a[i][2], a[i][3],
                      (a_base[i] + so) ^ (((ks << 1) + kA) << 4));
            #pragma unroll
            for (int j = 0; j < 4; j++) {
                uint32_t r0, r1, r2, r3;
                ldsm4(r0, r1, r2, r3, (b_base[j] + so) ^ (((ks << 1) + kB) << 4));
                b[2 * j][0] = r0;     b[2 * j][1] = r1;
                b[2 * j + 1][0] = r2; b[2 * j + 1][1] = r3;
            }
            #pragma unroll
            for (int i = 0; i < 4; i++)
                #pragma unroll
                for (int j = 0; j < 8; j++)
                    mma16816(acc[i][j], a[i], b[j]);
        }
        mbar_arrive(sb + MB_EMPTY(s));
        if (s == NSTAGE - 1) phase ^= 1;
    }

    // epilogue: per-column scale, fp32 store
    const int qr = lane >> 2, qc = lane & 3;
    float s0[8], s1[8];
    #pragma unroll
    for (int j = 0; j < 8; j++) {
        int c = n0 + wn + j * 8 + qc * 2;
        s0[j] = __ldg(&scale[c]);
        s1[j] = __ldg(&scale[c + 1]);
    }
    #pragma unroll
    for (int i = 0; i < 4; i++) {
        int rlo = m0 + wm + i * 16 + qr;
        #pragma unroll
        for (int j = 0; j < 8; j++) {
            int c = n0 + wn + j * 8 + qc * 2;
            float2 v;
            v.x = acc[i][j][0] * s0[j];
            v.y = acc[i][j][1] * s1[j];
            *reinterpret_cast<float2*>(out + (size_t)rlo * NDIM + c) = v;
            v.x = acc[i][j][2] * s0[j];
            v.y = acc[i][j][3] * s1[j];
            *reinterpret_cast<float2*>(out + (size_t)(rlo + 8) * NDIM + c) = v;
        }
    }
}

extern "C" void kernel_launch(void* const* d_in, const int* in_sizes, int n_in,
                              void* d_out, int out_size)
{
    const float* x     = (const float*)d_in[0];
    const int*   wp    = (const int*)d_in[1];
    const float* scale = (const float*)d_in[2];
    const float* zero  = (const float*)d_in[3];
    float* out = (float*)d_out;

    cudaFuncSetAttribute(aql_gemm, cudaFuncAttributeMaxDynamicSharedMemorySize,
                         (int)SMEM_BYTES);
    int grid = (MDIM / BM) * (NDIM / BN);   // 2752
    aql_gemm<<<grid, NT, SMEM_BYTES>>>(x, wp, scale, zero, out);
}